// round 12
// baseline (speedup 1.0000x reference)
#include <cuda_runtime.h>
#include <math.h>
#include <stdint.h>

#define B_ 16
#define N_ 1024
#define C_ 256

#define KC     32                  // k-chunk (floats)
#define STR    36                  // smem row stride (floats)
#define TILE   (128 * STR)         // floats per raw tile (18432 B)
#define STAGES 3
#define DYN_BYTES (STAGES * 2 * TILE * 4)   // 110592 B

// V transposed to [B][C][N]
static __device__ float g_Vt[(size_t)B_ * C_ * N_];

// ---------------------------------------------------------------------------
// mma.sync m16n8k8 tf32, row.col, fp32 accumulate
// ---------------------------------------------------------------------------
__device__ __forceinline__ void mma_tf32(float* d,
                                         float a0, float a1, float a2, float a3,
                                         float b0, float b1) {
    asm volatile(
        "mma.sync.aligned.m16n8k8.row.col.f32.tf32.tf32.f32 "
        "{%0,%1,%2,%3}, {%4,%5,%6,%7}, {%8,%9}, {%0,%1,%2,%3};"
        : "+f"(d[0]), "+f"(d[1]), "+f"(d[2]), "+f"(d[3])
        : "r"(__float_as_uint(a0)), "r"(__float_as_uint(a1)),
          "r"(__float_as_uint(a2)), "r"(__float_as_uint(a3)),
          "r"(__float_as_uint(b0)), "r"(__float_as_uint(b1)));
}

__device__ __forceinline__ float hi_part(float x) {
    return __uint_as_float(__float_as_uint(x) & 0xFFFFE000u);
}

// ---------------------------------------------------------------------------
// cp.async 16B gmem -> smem
// ---------------------------------------------------------------------------
__device__ __forceinline__ void cp16(uint32_t saddr, const float* g) {
    asm volatile("cp.async.ca.shared.global [%0], [%1], 16;"
                 :: "r"(saddr), "l"(g) : "memory");
}

__device__ __forceinline__ void load_tiles_async(
    const float* __restrict__ Ag, const float* __restrict__ Bg,
    int lda, int ldb, int aBase, int bBase, int k0,
    uint32_t sA, uint32_t sB, int tid)
{
#pragma unroll
    for (int e = 0; e < 4; e++) {
        int lin = tid + e * 256;
        int row = lin >> 3;            // 0..127
        int c4  = (lin & 7) * 4;       // 0..28
        uint32_t off = (uint32_t)(row * STR + c4) * 4;
        cp16(sA + off, &Ag[(size_t)(aBase + row) * lda + k0 + c4]);
        cp16(sB + off, &Bg[(size_t)(bBase + row) * ldb + k0 + c4]);
    }
    asm volatile("cp.async.commit_group;" ::: "memory");
}

// ---------------------------------------------------------------------------
// one k-chunk (KC=32): raw tiles -> register split -> 3xTF32 mma
// 8 warps (2x4), warp tile 64x32, 4x4 m16n8 tiles
// ---------------------------------------------------------------------------
__device__ __forceinline__ void compute_chunk(
    const float* __restrict__ As, const float* __restrict__ Bs,
    float acc[4][4][4], int wm, int wn, int g, int cq)
{
#pragma unroll
    for (int s = 0; s < KC; s += 8) {
        const int co = s + cq;
        float ah[4][4], al[4][4];
#pragma unroll
        for (int i = 0; i < 4; i++) {
            int idx = (wm * 64 + i * 16 + g) * STR + co;
            float r0 = As[idx];
            float r1 = As[idx + 8 * STR];
            float r2 = As[idx + 4];
            float r3 = As[idx + 8 * STR + 4];
            ah[i][0] = hi_part(r0); al[i][0] = r0 - ah[i][0];
            ah[i][1] = hi_part(r1); al[i][1] = r1 - ah[i][1];
            ah[i][2] = hi_part(r2); al[i][2] = r2 - ah[i][2];
            ah[i][3] = hi_part(r3); al[i][3] = r3 - ah[i][3];
        }
#pragma unroll
        for (int j = 0; j < 4; j++) {
            int bidx = (wn * 32 + j * 8 + g) * STR + co;
            float b0 = Bs[bidx];
            float b1 = Bs[bidx + 4];
            float bh0 = hi_part(b0), bl0 = b0 - bh0;
            float bh1 = hi_part(b1), bl1 = b1 - bh1;
#pragma unroll
            for (int i = 0; i < 4; i++)
                mma_tf32(acc[i][j], ah[i][0], ah[i][1], ah[i][2], ah[i][3], bh0, bh1);
#pragma unroll
            for (int i = 0; i < 4; i++)
                mma_tf32(acc[i][j], al[i][0], al[i][1], al[i][2], al[i][3], bh0, bh1);
#pragma unroll
            for (int i = 0; i < 4; i++)
                mma_tf32(acc[i][j], ah[i][0], ah[i][1], ah[i][2], ah[i][3], bl0, bl1);
        }
    }
}

// ---------------------------------------------------------------------------
// 3-stage cp.async mainloop: ONE __syncthreads per chunk.
// stage use at iter c: compute c%3, in-flight c+1 -> (c+1)%3, issue c+2 -> (c+2)%3
// ---------------------------------------------------------------------------
__device__ __forceinline__ void gemm_mainloop(
    const float* __restrict__ Ag, const float* __restrict__ Bg,
    int lda, int ldb, int aBase, int bBase, int nChunks,
    float* __restrict__ smem, uint32_t sbase,
    float acc[4][4][4], int tid, int wm, int wn, int g, int cq)
{
    // prologue: stages 0 and 1
    load_tiles_async(Ag, Bg, lda, ldb, aBase, bBase, 0,
                     sbase, sbase + (uint32_t)TILE * 4, tid);
    load_tiles_async(Ag, Bg, lda, ldb, aBase, bBase, KC,
                     sbase + (uint32_t)(2 * TILE) * 4,
                     sbase + (uint32_t)(3 * TILE) * 4, tid);

    for (int c = 0; c < nChunks; c++) {
        if (c + 1 < nChunks) {
            asm volatile("cp.async.wait_group 1;" ::: "memory");
        } else {
            asm volatile("cp.async.wait_group 0;" ::: "memory");
        }
        __syncthreads();
        const int cur = c % STAGES;
        compute_chunk(smem + cur * 2 * TILE, smem + (cur * 2 + 1) * TILE,
                      acc, wm, wn, g, cq);
        if (c + 2 < nChunks) {
            const int nxt = (c + 2) % STAGES;
            load_tiles_async(Ag, Bg, lda, ldb, aBase, bBase, (c + 2) * KC,
                             sbase + (uint32_t)(nxt * 2 * TILE) * 4,
                             sbase + (uint32_t)((nxt * 2 + 1) * TILE) * 4, tid);
        }
    }
}

// ---------------------------------------------------------------------------
// Kernel 0: transpose V -> g_Vt  [B][N][C] -> [B][C][N]
// ---------------------------------------------------------------------------
__global__ __launch_bounds__(256) void transpose_v_kernel(const float* __restrict__ V)
{
    __shared__ float t[32][33];
    const int b  = blockIdx.z;
    const int n0 = blockIdx.y * 32;
    const int c0 = blockIdx.x * 32;
    const float* Vb = V + (size_t)b * N_ * C_;
    float* Tb = g_Vt + (size_t)b * C_ * N_;
    const int x = threadIdx.x, y = threadIdx.y;
#pragma unroll
    for (int dy = 0; dy < 32; dy += 8)
        t[y + dy][x] = Vb[(size_t)(n0 + y + dy) * C_ + c0 + x];
    __syncthreads();
#pragma unroll
    for (int dy = 0; dy < 32; dy += 8)
        Tb[(size_t)(c0 + y + dy) * N_ + n0 + x] = t[x][y + dy];
}

// ---------------------------------------------------------------------------
// Kernel 1: attn = masked((Q K^T + dis) * 0.0625)
// ---------------------------------------------------------------------------
__global__ __launch_bounds__(256, 2) void qk_scores_kernel(
    const float* __restrict__ Q,
    const float* __restrict__ K,
    const float* __restrict__ dis,
    const int*   __restrict__ mask,
    float* __restrict__ attn)
{
    extern __shared__ float smem[];
    const uint32_t sbase = (uint32_t)__cvta_generic_to_shared(smem);

    const int b     = blockIdx.z;
    const int qBase = blockIdx.y * 128;
    const int kBase = blockIdx.x * 128;

    const int tid  = threadIdx.x;
    const int lane = tid & 31;
    const int w    = tid >> 5;
    const int wm   = w >> 2;
    const int wn   = w & 3;
    const int g    = lane >> 2;
    const int cq   = lane & 3;

    float acc[4][4][4];
#pragma unroll
    for (int i = 0; i < 4; i++)
#pragma unroll
        for (int j = 0; j < 4; j++)
#pragma unroll
            for (int r = 0; r < 4; r++) acc[i][j][r] = 0.0f;

    gemm_mainloop(Q + (size_t)b * N_ * C_, K + (size_t)b * N_ * C_,
                  C_, C_, qBase, kBase, C_ / KC,
                  smem, sbase, acc, tid, wm, wn, g, cq);

    // epilogue: add dis, scale, mask
#pragma unroll
    for (int i = 0; i < 4; i++) {
        int r0 = qBase + wm * 64 + i * 16 + g;
        int r1 = r0 + 8;
#pragma unroll
        for (int j = 0; j < 4; j++) {
            int col = kBase + wn * 32 + j * 8 + 2 * cq;
            size_t i0 = ((size_t)b * N_ + r0) * N_ + col;
            size_t i1 = ((size_t)b * N_ + r1) * N_ + col;
            float2 d0 = *reinterpret_cast<const float2*>(&dis[i0]);
            float2 d1 = *reinterpret_cast<const float2*>(&dis[i1]);
            int2   m0 = *reinterpret_cast<const int2*>(&mask[i0]);
            int2   m1 = *reinterpret_cast<const int2*>(&mask[i1]);
            float2 o0, o1;
            o0.x = m0.x ? -INFINITY : (acc[i][j][0] + d0.x) * 0.0625f;
            o0.y = m0.y ? -INFINITY : (acc[i][j][1] + d0.y) * 0.0625f;
            o1.x = m1.x ? -INFINITY : (acc[i][j][2] + d1.x) * 0.0625f;
            o1.y = m1.y ? -INFINITY : (acc[i][j][3] + d1.y) * 0.0625f;
            *reinterpret_cast<float2*>(&attn[i0]) = o0;
            *reinterpret_cast<float2*>(&attn[i1]) = o1;
        }
    }
}

// ---------------------------------------------------------------------------
// Kernel 2: row softmax (rows of 1024), shuffle-based, float4 I/O
// ---------------------------------------------------------------------------
__global__ __launch_bounds__(256) void softmax_kernel(float* __restrict__ attn)
{
    __shared__ float s1[8], s2[8];
    const size_t base = (size_t)blockIdx.x * N_;
    const int t = threadIdx.x;
    const int w = t >> 5, lane = t & 31;

    float4 v = *reinterpret_cast<const float4*>(&attn[base + t * 4]);

    float m = fmaxf(fmaxf(v.x, v.y), fmaxf(v.z, v.w));
#pragma unroll
    for (int o = 16; o; o >>= 1) m = fmaxf(m, __shfl_xor_sync(0xffffffffu, m, o));
    if (lane == 0) s1[w] = m;
    __syncthreads();
    float M = s1[0];
#pragma unroll
    for (int i = 1; i < 8; i++) M = fmaxf(M, s1[i]);

    float4 p;
    p.x = __expf(v.x - M); p.y = __expf(v.y - M);
    p.z = __expf(v.z - M); p.w = __expf(v.w - M);
    float s = (p.x + p.y) + (p.z + p.w);
#pragma unroll
    for (int o = 16; o; o >>= 1) s += __shfl_xor_sync(0xffffffffu, s, o);
    if (lane == 0) s2[w] = s;
    __syncthreads();
    float S = s2[0];
#pragma unroll
    for (int i = 1; i < 8; i++) S += s2[i];
    float inv = 1.0f / S;

    p.x *= inv; p.y *= inv; p.z *= inv; p.w *= inv;
    *reinterpret_cast<float4*>(&attn[base + t * 4]) = p;
}

// ---------------------------------------------------------------------------
// Kernel 3: p_val = p_attn @ V (B from g_Vt, K-major)
// ---------------------------------------------------------------------------
__global__ __launch_bounds__(256, 2) void pv_kernel(
    const float* __restrict__ P,
    float* __restrict__ out)
{
    extern __shared__ float smem[];
    const uint32_t sbase = (uint32_t)__cvta_generic_to_shared(smem);

    const int b     = blockIdx.z;
    const int qBase = blockIdx.y * 128;
    const int nBase = blockIdx.x * 128;

    const int tid  = threadIdx.x;
    const int lane = tid & 31;
    const int w    = tid >> 5;
    const int wm   = w >> 2;
    const int wn   = w & 3;
    const int g    = lane >> 2;
    const int cq   = lane & 3;

    float acc[4][4][4];
#pragma unroll
    for (int i = 0; i < 4; i++)
#pragma unroll
        for (int j = 0; j < 4; j++)
#pragma unroll
            for (int r = 0; r < 4; r++) acc[i][j][r] = 0.0f;

    gemm_mainloop(P + (size_t)b * N_ * N_, g_Vt + (size_t)b * C_ * N_,
                  N_, N_, qBase, nBase, N_ / KC,
                  smem, sbase, acc, tid, wm, wn, g, cq);

#pragma unroll
    for (int i = 0; i < 4; i++) {
        int r0 = qBase + wm * 64 + i * 16 + g;
        int r1 = r0 + 8;
#pragma unroll
        for (int j = 0; j < 4; j++) {
            int col = nBase + wn * 32 + j * 8 + 2 * cq;
            size_t i0 = ((size_t)b * N_ + r0) * C_ + col;
            size_t i1 = ((size_t)b * N_ + r1) * C_ + col;
            *reinterpret_cast<float2*>(&out[i0]) = make_float2(acc[i][j][0], acc[i][j][1]);
            *reinterpret_cast<float2*>(&out[i1]) = make_float2(acc[i][j][2], acc[i][j][3]);
        }
    }
}

// ---------------------------------------------------------------------------
// Launch
// ---------------------------------------------------------------------------
extern "C" void kernel_launch(void* const* d_in, const int* in_sizes, int n_in,
                              void* d_out, int out_size)
{
    const float* Q    = (const float*)d_in[0];
    const float* K    = (const float*)d_in[1];
    const float* V    = (const float*)d_in[2];
    const int*   mask = (const int*)d_in[3];
    const float* dis  = (const float*)d_in[4];

    float* out    = (float*)d_out;
    float* p_val  = out;                          // [B, N, C]
    float* p_attn = out + (size_t)B_ * N_ * C_;   // [B, N, N]

    cudaFuncSetAttribute(qk_scores_kernel,
                         cudaFuncAttributeMaxDynamicSharedMemorySize, DYN_BYTES);
    cudaFuncSetAttribute(pv_kernel,
                         cudaFuncAttributeMaxDynamicSharedMemorySize, DYN_BYTES);

    transpose_v_kernel<<<dim3(C_ / 32, N_ / 32, B_), dim3(32, 8)>>>(V);
    qk_scores_kernel<<<dim3(N_ / 128, N_ / 128, B_), 256, DYN_BYTES>>>(Q, K, dis, mask, p_attn);
    softmax_kernel<<<B_ * N_, 256>>>(p_attn);
    pv_kernel<<<dim3(C_ / 128, N_ / 128, B_), 256, DYN_BYTES>>>(p_attn, p_val);
}

// round 13
// speedup vs baseline: 1.5094x; 1.5094x over previous
#include <cuda_runtime.h>
#include <math.h>
#include <stdint.h>

#define B_ 16
#define N_ 1024
#define C_ 256

#define KC    32                  // k-chunk (floats)
#define STR   40                  // smem row stride (floats): conflict-free for LDS.64
#define TILE  (128 * STR)         // floats per raw tile (20480 B)
#define DYN_BYTES (4 * TILE * 4)  // 2 buffers x (A,B) = 163840/2... = 81920 B

// V transposed to [B][C][N]
static __device__ float g_Vt[(size_t)B_ * C_ * N_];

// ---------------------------------------------------------------------------
// mma.sync m16n8k16 bf16, row.col, fp32 accumulate
// ---------------------------------------------------------------------------
__device__ __forceinline__ void mma_bf16(float* d,
                                         uint32_t a0, uint32_t a1,
                                         uint32_t a2, uint32_t a3,
                                         uint32_t b0, uint32_t b1) {
    asm volatile(
        "mma.sync.aligned.m16n8k16.row.col.f32.bf16.bf16.f32 "
        "{%0,%1,%2,%3}, {%4,%5,%6,%7}, {%8,%9}, {%0,%1,%2,%3};"
        : "+f"(d[0]), "+f"(d[1]), "+f"(d[2]), "+f"(d[3])
        : "r"(a0), "r"(a1), "r"(a2), "r"(a3), "r"(b0), "r"(b1));
}

// split a float2 (k, k+1) into packed bf16x2 hi (exact trunc) and lo (RN)
__device__ __forceinline__ void pack_split(float2 v, uint32_t& hi, uint32_t& lo) {
    uint32_t u0 = __float_as_uint(v.x) & 0xFFFF0000u;
    uint32_t u1 = __float_as_uint(v.y) & 0xFFFF0000u;
    hi = __byte_perm(u0, u1, 0x7632);          // low16=bf16(v.x), high16=bf16(v.y)
    float l0 = v.x - __uint_as_float(u0);
    float l1 = v.y - __uint_as_float(u1);
    asm("cvt.rn.bf16x2.f32 %0, %1, %2;" : "=r"(lo) : "f"(l1), "f"(l0));
}

// ---------------------------------------------------------------------------
// cp.async 16B gmem -> smem
// ---------------------------------------------------------------------------
__device__ __forceinline__ void cp16(uint32_t saddr, const float* g) {
    asm volatile("cp.async.ca.shared.global [%0], [%1], 16;"
                 :: "r"(saddr), "l"(g) : "memory");
}

__device__ __forceinline__ void load_tiles_async(
    const float* __restrict__ Ag, const float* __restrict__ Bg,
    int lda, int ldb, int aBase, int bBase, int k0,
    uint32_t sA, uint32_t sB, int tid)
{
#pragma unroll
    for (int e = 0; e < 4; e++) {
        int lin = tid + e * 256;
        int row = lin >> 3;            // 0..127
        int c4  = (lin & 7) * 4;       // 0..28
        uint32_t off = (uint32_t)(row * STR + c4) * 4;
        cp16(sA + off, &Ag[(size_t)(aBase + row) * lda + k0 + c4]);
        cp16(sB + off, &Bg[(size_t)(bBase + row) * ldb + k0 + c4]);
    }
    asm volatile("cp.async.commit_group;" ::: "memory");
}

// ---------------------------------------------------------------------------
// one k-chunk (KC=32): 2 s-steps of k16, 3-pass bf16 split
// 8 warps (2x4), warp tile 64x32, 4x4 m16n8 tiles
// ---------------------------------------------------------------------------
__device__ __forceinline__ void compute_chunk(
    const float* __restrict__ As, const float* __restrict__ Bs,
    float acc[4][4][4], int wm, int wn, int g, int cq)
{
#pragma unroll
    for (int s = 0; s < KC; s += 16) {
        const int co = s + 2 * cq;
        uint32_t ah[4][4], al[4][4];
#pragma unroll
        for (int i = 0; i < 4; i++) {
            int r0 = (wm * 64 + i * 16 + g) * STR + co;
            int r1 = r0 + 8 * STR;
            float2 x0 = *reinterpret_cast<const float2*>(&As[r0]);      // row g,   k..k+1
            float2 x1 = *reinterpret_cast<const float2*>(&As[r1]);      // row g+8, k..k+1
            float2 x2 = *reinterpret_cast<const float2*>(&As[r0 + 8]);  // row g,   k+8..k+9
            float2 x3 = *reinterpret_cast<const float2*>(&As[r1 + 8]);  // row g+8, k+8..k+9
            pack_split(x0, ah[i][0], al[i][0]);
            pack_split(x1, ah[i][1], al[i][1]);
            pack_split(x2, ah[i][2], al[i][2]);
            pack_split(x3, ah[i][3], al[i][3]);
        }
#pragma unroll
        for (int j = 0; j < 4; j++) {
            int cb = (wn * 32 + j * 8 + g) * STR + co;
            float2 y0 = *reinterpret_cast<const float2*>(&Bs[cb]);
            float2 y1 = *reinterpret_cast<const float2*>(&Bs[cb + 8]);
            uint32_t bh0, bl0, bh1, bl1;
            pack_split(y0, bh0, bl0);
            pack_split(y1, bh1, bl1);
            // pass 1: hi*hi
#pragma unroll
            for (int i = 0; i < 4; i++)
                mma_bf16(acc[i][j], ah[i][0], ah[i][1], ah[i][2], ah[i][3], bh0, bh1);
            // pass 2: lo*hi
#pragma unroll
            for (int i = 0; i < 4; i++)
                mma_bf16(acc[i][j], al[i][0], al[i][1], al[i][2], al[i][3], bh0, bh1);
            // pass 3: hi*lo
#pragma unroll
            for (int i = 0; i < 4; i++)
                mma_bf16(acc[i][j], ah[i][0], ah[i][1], ah[i][2], ah[i][3], bl0, bl1);
        }
    }
}

// ---------------------------------------------------------------------------
// 2-stage cp.async mainloop (R10 structure)
// ---------------------------------------------------------------------------
__device__ __forceinline__ void gemm_mainloop(
    const float* __restrict__ Ag, const float* __restrict__ Bg,
    int lda, int ldb, int aBase, int bBase, int nChunks,
    float* __restrict__ smem, uint32_t sbase,
    float acc[4][4][4], int tid, int wm, int wn, int g, int cq)
{
    load_tiles_async(Ag, Bg, lda, ldb, aBase, bBase, 0,
                     sbase, sbase + (uint32_t)TILE * 4, tid);

    for (int c = 0; c < nChunks; c++) {
        const int cur = c & 1;
        if (c + 1 < nChunks) {
            const int nxt = cur ^ 1;
            load_tiles_async(Ag, Bg, lda, ldb, aBase, bBase, (c + 1) * KC,
                             sbase + (uint32_t)(nxt * 2 * TILE) * 4,
                             sbase + (uint32_t)((nxt * 2 + 1) * TILE) * 4, tid);
            asm volatile("cp.async.wait_group 1;" ::: "memory");
        } else {
            asm volatile("cp.async.wait_group 0;" ::: "memory");
        }
        __syncthreads();
        compute_chunk(smem + cur * 2 * TILE, smem + (cur * 2 + 1) * TILE,
                      acc, wm, wn, g, cq);
        __syncthreads();
    }
}

// ---------------------------------------------------------------------------
// Kernel 0: transpose V -> g_Vt  [B][N][C] -> [B][C][N]
// ---------------------------------------------------------------------------
__global__ __launch_bounds__(256) void transpose_v_kernel(const float* __restrict__ V)
{
    __shared__ float t[32][33];
    const int b  = blockIdx.z;
    const int n0 = blockIdx.y * 32;
    const int c0 = blockIdx.x * 32;
    const float* Vb = V + (size_t)b * N_ * C_;
    float* Tb = g_Vt + (size_t)b * C_ * N_;
    const int x = threadIdx.x, y = threadIdx.y;
#pragma unroll
    for (int dy = 0; dy < 32; dy += 8)
        t[y + dy][x] = Vb[(size_t)(n0 + y + dy) * C_ + c0 + x];
    __syncthreads();
#pragma unroll
    for (int dy = 0; dy < 32; dy += 8)
        Tb[(size_t)(c0 + y + dy) * N_ + n0 + x] = t[x][y + dy];
}

// ---------------------------------------------------------------------------
// Kernel 1: attn = masked((Q K^T + dis) * 0.0625)
// ---------------------------------------------------------------------------
__global__ __launch_bounds__(256, 2) void qk_scores_kernel(
    const float* __restrict__ Q,
    const float* __restrict__ K,
    const float* __restrict__ dis,
    const int*   __restrict__ mask,
    float* __restrict__ attn)
{
    extern __shared__ float smem[];
    const uint32_t sbase = (uint32_t)__cvta_generic_to_shared(smem);

    const int b     = blockIdx.z;
    const int qBase = blockIdx.y * 128;
    const int kBase = blockIdx.x * 128;

    const int tid  = threadIdx.x;
    const int lane = tid & 31;
    const int w    = tid >> 5;
    const int wm   = w >> 2;
    const int wn   = w & 3;
    const int g    = lane >> 2;
    const int cq   = lane & 3;

    float acc[4][4][4];
#pragma unroll
    for (int i = 0; i < 4; i++)
#pragma unroll
        for (int j = 0; j < 4; j++)
#pragma unroll
            for (int r = 0; r < 4; r++) acc[i][j][r] = 0.0f;

    gemm_mainloop(Q + (size_t)b * N_ * C_, K + (size_t)b * N_ * C_,
                  C_, C_, qBase, kBase, C_ / KC,
                  smem, sbase, acc, tid, wm, wn, g, cq);

    // epilogue: add dis, scale, mask
#pragma unroll
    for (int i = 0; i < 4; i++) {
        int r0 = qBase + wm * 64 + i * 16 + g;
        int r1 = r0 + 8;
#pragma unroll
        for (int j = 0; j < 4; j++) {
            int col = kBase + wn * 32 + j * 8 + 2 * cq;
            size_t i0 = ((size_t)b * N_ + r0) * N_ + col;
            size_t i1 = ((size_t)b * N_ + r1) * N_ + col;
            float2 d0 = *reinterpret_cast<const float2*>(&dis[i0]);
            float2 d1 = *reinterpret_cast<const float2*>(&dis[i1]);
            int2   m0 = *reinterpret_cast<const int2*>(&mask[i0]);
            int2   m1 = *reinterpret_cast<const int2*>(&mask[i1]);
            float2 o0, o1;
            o0.x = m0.x ? -INFINITY : (acc[i][j][0] + d0.x) * 0.0625f;
            o0.y = m0.y ? -INFINITY : (acc[i][j][1] + d0.y) * 0.0625f;
            o1.x = m1.x ? -INFINITY : (acc[i][j][2] + d1.x) * 0.0625f;
            o1.y = m1.y ? -INFINITY : (acc[i][j][3] + d1.y) * 0.0625f;
            *reinterpret_cast<float2*>(&attn[i0]) = o0;
            *reinterpret_cast<float2*>(&attn[i1]) = o1;
        }
    }
}

// ---------------------------------------------------------------------------
// Kernel 2: row softmax (rows of 1024), shuffle-based, float4 I/O
// ---------------------------------------------------------------------------
__global__ __launch_bounds__(256) void softmax_kernel(float* __restrict__ attn)
{
    __shared__ float s1[8], s2[8];
    const size_t base = (size_t)blockIdx.x * N_;
    const int t = threadIdx.x;
    const int w = t >> 5, lane = t & 31;

    float4 v = *reinterpret_cast<const float4*>(&attn[base + t * 4]);

    float m = fmaxf(fmaxf(v.x, v.y), fmaxf(v.z, v.w));
#pragma unroll
    for (int o = 16; o; o >>= 1) m = fmaxf(m, __shfl_xor_sync(0xffffffffu, m, o));
    if (lane == 0) s1[w] = m;
    __syncthreads();
    float M = s1[0];
#pragma unroll
    for (int i = 1; i < 8; i++) M = fmaxf(M, s1[i]);

    float4 p;
    p.x = __expf(v.x - M); p.y = __expf(v.y - M);
    p.z = __expf(v.z - M); p.w = __expf(v.w - M);
    float s = (p.x + p.y) + (p.z + p.w);
#pragma unroll
    for (int o = 16; o; o >>= 1) s += __shfl_xor_sync(0xffffffffu, s, o);
    if (lane == 0) s2[w] = s;
    __syncthreads();
    float S = s2[0];
#pragma unroll
    for (int i = 1; i < 8; i++) S += s2[i];
    float inv = 1.0f / S;

    p.x *= inv; p.y *= inv; p.z *= inv; p.w *= inv;
    *reinterpret_cast<float4*>(&attn[base + t * 4]) = p;
}

// ---------------------------------------------------------------------------
// Kernel 3: p_val = p_attn @ V (B from g_Vt, K-major)
// ---------------------------------------------------------------------------
__global__ __launch_bounds__(256, 2) void pv_kernel(
    const float* __restrict__ P,
    float* __restrict__ out)
{
    extern __shared__ float smem[];
    const uint32_t sbase = (uint32_t)__cvta_generic_to_shared(smem);

    const int b     = blockIdx.z;
    const int qBase = blockIdx.y * 128;
    const int nBase = blockIdx.x * 128;

    const int tid  = threadIdx.x;
    const int lane = tid & 31;
    const int w    = tid >> 5;
    const int wm   = w >> 2;
    const int wn   = w & 3;
    const int g    = lane >> 2;
    const int cq   = lane & 3;

    float acc[4][4][4];
#pragma unroll
    for (int i = 0; i < 4; i++)
#pragma unroll
        for (int j = 0; j < 4; j++)
#pragma unroll
            for (int r = 0; r < 4; r++) acc[i][j][r] = 0.0f;

    gemm_mainloop(P + (size_t)b * N_ * N_, g_Vt + (size_t)b * C_ * N_,
                  N_, N_, qBase, nBase, N_ / KC,
                  smem, sbase, acc, tid, wm, wn, g, cq);

#pragma unroll
    for (int i = 0; i < 4; i++) {
        int r0 = qBase + wm * 64 + i * 16 + g;
        int r1 = r0 + 8;
#pragma unroll
        for (int j = 0; j < 4; j++) {
            int col = nBase + wn * 32 + j * 8 + 2 * cq;
            size_t i0 = ((size_t)b * N_ + r0) * C_ + col;
            size_t i1 = ((size_t)b * N_ + r1) * C_ + col;
            *reinterpret_cast<float2*>(&out[i0]) = make_float2(acc[i][j][0], acc[i][j][1]);
            *reinterpret_cast<float2*>(&out[i1]) = make_float2(acc[i][j][2], acc[i][j][3]);
        }
    }
}

// ---------------------------------------------------------------------------
// Launch
// ---------------------------------------------------------------------------
extern "C" void kernel_launch(void* const* d_in, const int* in_sizes, int n_in,
                              void* d_out, int out_size)
{
    const float* Q    = (const float*)d_in[0];
    const float* K    = (const float*)d_in[1];
    const float* V    = (const float*)d_in[2];
    const int*   mask = (const int*)d_in[3];
    const float* dis  = (const float*)d_in[4];

    float* out    = (float*)d_out;
    float* p_val  = out;                          // [B, N, C]
    float* p_attn = out + (size_t)B_ * N_ * C_;   // [B, N, N]

    cudaFuncSetAttribute(qk_scores_kernel,
                         cudaFuncAttributeMaxDynamicSharedMemorySize, DYN_BYTES);
    cudaFuncSetAttribute(pv_kernel,
                         cudaFuncAttributeMaxDynamicSharedMemorySize, DYN_BYTES);

    transpose_v_kernel<<<dim3(C_ / 32, N_ / 32, B_), dim3(32, 8)>>>(V);
    qk_scores_kernel<<<dim3(N_ / 128, N_ / 128, B_), 256, DYN_BYTES>>>(Q, K, dis, mask, p_attn);
    softmax_kernel<<<B_ * N_, 256>>>(p_attn);
    pv_kernel<<<dim3(C_ / 128, N_ / 128, B_), 256, DYN_BYTES>>>(p_attn, p_val);
}